// round 8
// baseline (speedup 1.0000x reference)
#include <cuda_runtime.h>

#define GG    4096
#define MM    50
#define KK    30
#define HH    32
#define FIN   128
#define EPG   400      // edges per graph
#define DLAT  97
#define DDENSE 352
#define NN    (GG * MM)

// static device scratch (no allocs allowed)
__device__ float g_t0[(size_t)NN * HH];   // x @ W0
__device__ float g_z[(size_t)GG * DDENSE];

// ---------------------------------------------------------------------------
// Kernel A: t0 = x @ W0 ([N,128] @ [128,32]). 64 rows/CTA, smem-staged input.
// (unchanged from round 7: measured 72 us)
// ---------------------------------------------------------------------------
__global__ void __launch_bounds__(256)
xw0_kernel(const float* __restrict__ x, const float* __restrict__ W0,
           float* __restrict__ t0) {
    __shared__ __align__(16) float xs[64 * FIN];   // 32 KB
    const int tid = threadIdx.x, lane = tid & 31, warp = tid >> 5;
    const size_t base = (size_t)blockIdx.x * 64;

    {
        const float4* s = reinterpret_cast<const float4*>(x + base * FIN);
        float4* d = reinterpret_cast<float4*>(xs);
#pragma unroll
        for (int i = tid; i < 64 * FIN / 4; i += 256) d[i] = s[i];
    }
    __syncthreads();

    float acc[8] = {0.f, 0.f, 0.f, 0.f, 0.f, 0.f, 0.f, 0.f};
    const float* xr = xs + warp * 8 * FIN;
#pragma unroll 4
    for (int k = 0; k < FIN; k += 4) {
        float wa = __ldg(&W0[(k + 0) * HH + lane]);
        float wb = __ldg(&W0[(k + 1) * HH + lane]);
        float wc = __ldg(&W0[(k + 2) * HH + lane]);
        float wd = __ldg(&W0[(k + 3) * HH + lane]);
#pragma unroll
        for (int j = 0; j < 8; j++) {
            float4 xv = *reinterpret_cast<const float4*>(&xr[j * FIN + k]);
            acc[j] = fmaf(xv.x, wa, fmaf(xv.y, wb, fmaf(xv.z, wc, fmaf(xv.w, wd, acc[j]))));
        }
    }
    float* o = t0 + (base + (size_t)warp * 8) * HH + lane;
#pragma unroll
    for (int j = 0; j < 8; j++) o[j * HH] = acc[j];
}

// ---------------------------------------------------------------------------
// Kernel B: per-graph GCN agg1 + layers 2-4 + sort-pool + conv1/conv2.
// W1/W2/C1w staged in smem (L1D carveout too small to keep them cached).
// ---------------------------------------------------------------------------
struct Smem {
    alignas(16) float  h[MM * HH];       // 6400
    alignas(16) float  tmp[MM * HH];     // 6400
    alignas(16) float  W1s[HH * HH];     // 4096
    alignas(16) float  W2s[HH * HH];     // 4096
    alignas(16) float  C1ws[16 * DLAT];  // 6208
    float2 epack[EPG];                   // 3200
    float  lat[MM * DLAT];               // 19400 (stride 97: conflict-free col access)
    float  z1[16 * KK];                  // 1920
    float  pooled[16 * 15];              // 960
    float  dinv[MM];
    float  h4v[MM];
    int    rp[MM + 1];
    int    cnt[MM];
    int    cnt2[MM];
    int    sel[KK];
};  // ~53.8 KB -> 4 CTAs/SM

// h[M,32](smem) @ W[32,32](smem) -> tmp[M,32]. Warp tile: 7 nodes x 32 ch.
__device__ __forceinline__ void gcn_matmul32(const float* __restrict__ in,
                                             const float* __restrict__ Ws,
                                             float* __restrict__ tmp,
                                             int warp, int lane) {
    int nbase = warp * 7;
    if (nbase >= MM) return;
    int ncnt = MM - nbase; if (ncnt > 7) ncnt = 7;
    float acc[7] = {0.f, 0.f, 0.f, 0.f, 0.f, 0.f, 0.f};
#pragma unroll 4
    for (int k = 0; k < HH; k += 4) {
        float wa = Ws[(k + 0) * HH + lane];
        float wb = Ws[(k + 1) * HH + lane];
        float wc = Ws[(k + 2) * HH + lane];
        float wd = Ws[(k + 3) * HH + lane];
#pragma unroll
        for (int j = 0; j < 7; j++) {
            if (j < ncnt) {
                float4 xv = *reinterpret_cast<const float4*>(&in[(nbase + j) * HH + k]);
                acc[j] = fmaf(xv.x, wa, fmaf(xv.y, wb, fmaf(xv.z, wc, fmaf(xv.w, wd, acc[j]))));
            }
        }
    }
    for (int j = 0; j < ncnt; j++) tmp[(nbase + j) * HH + lane] = acc[j];
}

// gather-aggregate (CSR by dst) + self loop + bias + tanh -> h and lat column block
__device__ __forceinline__ void gcn_agg(Smem& s, int coloff, float bias,
                                        int warp, int lane) {
    for (int n = warp; n < MM; n += 8) {
        float di = s.dinv[n];
        float a = s.tmp[n * HH + lane] * di * di;
        int e1 = s.rp[n + 1];
        for (int e = s.rp[n]; e < e1; e++) {
            float2 p = s.epack[e];
            a = fmaf(s.tmp[__float_as_int(p.x) * HH + lane], p.y, a);
        }
        float r = tanhf(a + bias);
        s.lat[n * DLAT + coloff + lane] = r;
        s.h[n * HH + lane] = r;
    }
}

__global__ void __launch_bounds__(256, 4)
graph_kernel(const float* __restrict__ t0, const int* __restrict__ ei,
             const float* __restrict__ b0,
             const float* __restrict__ W1, const float* __restrict__ b1,
             const float* __restrict__ W2, const float* __restrict__ b2,
             const float* __restrict__ W3, const float* __restrict__ b3,
             const float* __restrict__ C1w, const float* __restrict__ C1b,
             const float* __restrict__ C2w, const float* __restrict__ C2b,
             int E) {
    extern __shared__ __align__(16) char raw[];
    Smem& s = *reinterpret_cast<Smem*>(raw);
    const int tid = threadIdx.x, lane = tid & 31, warp = tid >> 5;
    const int g = blockIdx.x;

    // ---- stage t0 slice + weights (coalesced), init counters ----
    {
        const float4* tsrc = reinterpret_cast<const float4*>(t0 + (size_t)g * MM * HH);
        float4* tdst = reinterpret_cast<float4*>(s.tmp);
        for (int i = tid; i < MM * HH / 4; i += 256) tdst[i] = tsrc[i];

        const float4* w1s = reinterpret_cast<const float4*>(W1);
        const float4* w2s = reinterpret_cast<const float4*>(W2);
        float4* w1d = reinterpret_cast<float4*>(s.W1s);
        float4* w2d = reinterpret_cast<float4*>(s.W2s);
        for (int i = tid; i < HH * HH / 4; i += 256) { w1d[i] = w1s[i]; w2d[i] = w2s[i]; }
        for (int i = tid; i < 16 * DLAT; i += 256) s.C1ws[i] = __ldg(&C1w[i]);
    }
    if (tid < MM) { s.cnt[tid] = 1; s.cnt2[tid] = 0; }  // self loop in cnt
    __syncthreads();

    // ---- degree count (read dst directly from global) ----
    const int ebase = g * EPG;
    for (int e = tid; e < EPG; e += 256) {
        int d = __ldg(&ei[E + ebase + e]) - g * MM;
        atomicAdd(&s.cnt[d], 1);
    }
    __syncthreads();

    // ---- dinv + warp-parallel exclusive scan of (cnt-1) -> rp ----
    if (tid >= 64 && tid < 64 + MM) s.dinv[tid - 64] = rsqrtf((float)s.cnt[tid - 64]);
    if (warp == 0) {
        int a = (lane < MM) ? (s.cnt[lane] - 1) : 0;
        int b = (lane + 32 < MM) ? (s.cnt[lane + 32] - 1) : 0;
        int sa = a, sb = b;
#pragma unroll
        for (int o = 1; o < 32; o <<= 1) {
            int ta = __shfl_up_sync(0xffffffffu, sa, o);
            int tb = __shfl_up_sync(0xffffffffu, sb, o);
            if (lane >= o) { sa += ta; sb += tb; }
        }
        int tot_a = __shfl_sync(0xffffffffu, sa, 31);
        s.rp[lane] = sa - a;
        if (lane + 32 < MM) s.rp[lane + 32] = tot_a + sb - b;
        if (lane == 31) s.rp[MM] = tot_a + sb;
    }
    __syncthreads();

    // ---- build CSR grouped by dst (re-read edges; L2-hot) ----
    for (int e = tid; e < EPG; e += 256) {
        int sl = __ldg(&ei[ebase + e]) - g * MM;
        int d  = __ldg(&ei[E + ebase + e]) - g * MM;
        int pos = s.rp[d] + atomicAdd(&s.cnt2[d], 1);
        s.epack[pos] = make_float2(__int_as_float(sl), s.dinv[sl] * s.dinv[d]);
    }
    __syncthreads();

    // ---- layer 1 aggregation (t0 already = x@W0) ----
    gcn_agg(s, 0, __ldg(&b0[lane]), warp, lane);
    __syncthreads();

    // ---- layers 2-3 (weights from smem) ----
    gcn_matmul32(s.h, s.W1s, s.tmp, warp, lane);
    __syncthreads();
    gcn_agg(s, 32, __ldg(&b1[lane]), warp, lane);
    __syncthreads();

    gcn_matmul32(s.h, s.W2s, s.tmp, warp, lane);
    __syncthreads();
    gcn_agg(s, 64, __ldg(&b2[lane]), warp, lane);
    __syncthreads();

    // ---- layer 4: H=32 -> 1 ----
    {
        float w3 = __ldg(&W3[lane]);
        for (int n = warp; n < MM; n += 8) {
            float v = s.h[n * HH + lane] * w3;
#pragma unroll
            for (int o = 16; o; o >>= 1) v += __shfl_xor_sync(0xffffffffu, v, o);
            if (lane == 0) s.tmp[n] = v;
        }
    }
    __syncthreads();
    if (tid < MM) {
        int n = tid;
        float di = s.dinv[n];
        float a = s.tmp[n] * di * di;
        int e1 = s.rp[n + 1];
        for (int e = s.rp[n]; e < e1; e++) {
            float2 p = s.epack[e];
            a = fmaf(s.tmp[__float_as_int(p.x)], p.y, a);
        }
        float r = tanhf(a + __ldg(&b3[0]));
        s.lat[n * DLAT + 96] = r;
        s.h4v[n] = r;
    }
    __syncthreads();

    // ---- sort-pool: exact rank == stable argsort(-h4) ----
    if (tid < MM) {
        float vi = s.h4v[tid];
        int r = 0;
        for (int j = 0; j < MM; j++) {
            float vj = s.h4v[j];
            r += (vj > vi) || (vj == vi && j < tid);
        }
        if (r < KK) s.sel[r] = tid;
    }
    __syncthreads();

    // ---- conv1 (per-slot 97-dot, all-smem) + relu ----
    for (int o = tid; o < 16 * KK; o += 256) {
        int t = o % KK, c = o / KK;
        const float* lr = &s.lat[s.sel[t] * DLAT];
        const float* cw = &s.C1ws[c * DLAT];
        float a = __ldg(&C1b[c]);
#pragma unroll 4
        for (int d = 0; d < DLAT; d++) a = fmaf(lr[d], cw[d], a);
        s.z1[c * KK + t] = fmaxf(a, 0.f);
    }
    __syncthreads();

    // ---- maxpool(2,2) ----
    if (tid < 16 * 15) {
        int u = tid % 15, c = tid / 15;
        s.pooled[c * 15 + u] = fmaxf(s.z1[c * KK + 2 * u], s.z1[c * KK + 2 * u + 1]);
    }
    __syncthreads();

    // ---- conv2 (16->32, k=5) + relu -> global scratch ----
    for (int o2 = tid; o2 < DDENSE; o2 += 256) {
        int o = o2 / 11, u = o2 % 11;
        float a = __ldg(&C2b[o]);
#pragma unroll
        for (int i = 0; i < 16; i++) {
            const float* pw = &C2w[(o * 16 + i) * 5];
            const float* pp = &s.pooled[i * 15 + u];
#pragma unroll
            for (int k2 = 0; k2 < 5; k2++) a = fmaf(pp[k2], __ldg(&pw[k2]), a);
        }
        g_z[(size_t)g * DDENSE + o2] = fmaxf(a, 0.f);
    }
}

// ---------------------------------------------------------------------------
// Kernel C: fused dense. 8 graphs / CTA, 128 threads (unchanged).
// ---------------------------------------------------------------------------
__global__ void __launch_bounds__(128)
dense_kernel(const float* __restrict__ L1w, const float* __restrict__ L1b,
             const float* __restrict__ L2w, const float* __restrict__ L2b,
             float* __restrict__ out) {
    __shared__ __align__(16) float zs[8][DDENSE];
    __shared__ float red[4][8];
    const int tid = threadIdx.x, lane = tid & 31, warp = tid >> 5;
    const int gbase = blockIdx.x * 8;

    {
        const float4* zsrc = reinterpret_cast<const float4*>(&g_z[(size_t)gbase * DDENSE]);
        float4* zdst = reinterpret_cast<float4*>(&zs[0][0]);
        for (int i = tid; i < 8 * DDENSE / 4; i += 128) zdst[i] = zsrc[i];
    }
    __syncthreads();

    const int ch = warp * 32 + lane;
    float acc[8];
    float l1b = __ldg(&L1b[ch]);
#pragma unroll
    for (int j = 0; j < 8; j++) acc[j] = l1b;

#pragma unroll 2
    for (int d = 0; d < DDENSE; d += 4) {
        float w0 = __ldg(&L1w[(d + 0) * 128 + ch]);
        float w1 = __ldg(&L1w[(d + 1) * 128 + ch]);
        float w2 = __ldg(&L1w[(d + 2) * 128 + ch]);
        float w3 = __ldg(&L1w[(d + 3) * 128 + ch]);
#pragma unroll
        for (int j = 0; j < 8; j++) {
            float4 zv = *reinterpret_cast<const float4*>(&zs[j][d]);
            acc[j] = fmaf(zv.x, w0, fmaf(zv.y, w1, fmaf(zv.z, w2, fmaf(zv.w, w3, acc[j]))));
        }
    }

    float w2v = __ldg(&L2w[ch]);
#pragma unroll
    for (int j = 0; j < 8; j++) {
        float p = fmaxf(acc[j], 0.f) * w2v;
#pragma unroll
        for (int o = 16; o; o >>= 1) p += __shfl_xor_sync(0xffffffffu, p, o);
        if (lane == 0) red[warp][j] = p;
    }
    __syncthreads();

    if (tid < 8) {
        out[gbase + tid] = red[0][tid] + red[1][tid] + red[2][tid] + red[3][tid]
                         + __ldg(&L2b[0]);
    }
}

extern "C" void kernel_launch(void* const* d_in, const int* in_sizes, int n_in,
                              void* d_out, int out_size) {
    const float* x   = (const float*)d_in[0];
    const int*   ei  = (const int*)d_in[1];
    // d_in[2] = batch (unused; graphs are contiguous equal-size blocks)
    const float* W0  = (const float*)d_in[3];
    const float* b0  = (const float*)d_in[4];
    const float* W1  = (const float*)d_in[5];
    const float* b1  = (const float*)d_in[6];
    const float* W2  = (const float*)d_in[7];
    const float* b2  = (const float*)d_in[8];
    const float* W3  = (const float*)d_in[9];
    const float* b3  = (const float*)d_in[10];
    const float* C1w = (const float*)d_in[11];
    const float* C1b = (const float*)d_in[12];
    const float* C2w = (const float*)d_in[13];
    const float* C2b = (const float*)d_in[14];
    const float* L1w = (const float*)d_in[15];
    const float* L1b = (const float*)d_in[16];
    const float* L2w = (const float*)d_in[17];
    const float* L2b = (const float*)d_in[18];

    const int E = in_sizes[1] / 2;

    float* t0;
    cudaGetSymbolAddress((void**)&t0, g_t0);

    const int smem = (int)sizeof(Smem);
    cudaFuncSetAttribute(graph_kernel, cudaFuncAttributeMaxDynamicSharedMemorySize, smem);

    xw0_kernel<<<NN / 64, 256>>>(x, W0, t0);
    graph_kernel<<<GG, 256, smem>>>(t0, ei, b0, W1, b1, W2, b2, W3, b3,
                                    C1w, C1b, C2w, C2b, E);
    dense_kernel<<<GG / 8, 128>>>(L1w, L1b, L2w, L2b, (float*)d_out);
}

// round 9
// speedup vs baseline: 1.0436x; 1.0436x over previous
#include <cuda_runtime.h>

#define GG    4096
#define MM    50
#define KK    30
#define HH    32
#define FIN   128
#define EPG   400      // edges per graph
#define DLAT  97
#define DDENSE 352
#define NN    (GG * MM)

typedef unsigned long long ull;

// ---- packed fp32x2 helpers (exact fp32, 2 FMAs per instruction) ----
__device__ __forceinline__ ull pack2(float a, float b) {
    ull r; asm("mov.b64 %0, {%1, %2};" : "=l"(r) : "f"(a), "f"(b)); return r;
}
__device__ __forceinline__ void fma2(ull& d, ull a, ull b) {
    asm("fma.rn.f32x2 %0, %1, %2, %0;" : "+l"(d) : "l"(a), "l"(b));
}
__device__ __forceinline__ float hsum2(ull v) {
    float lo, hi; asm("mov.b64 {%0, %1}, %2;" : "=f"(lo), "=f"(hi) : "l"(v));
    return lo + hi;
}
__device__ __forceinline__ ull d2u(double d) { return __double_as_longlong(d); }

// static device scratch (no allocs allowed)
__device__ float g_t0[(size_t)NN * HH];   // x @ W0
__device__ float g_z[(size_t)GG * DDENSE];

// ---------------------------------------------------------------------------
// Kernel A: t0 = x @ W0 ([N,128] @ [128,32]). 64 rows/CTA, smem-staged input,
// f32x2 packed along k (pairs contiguous in row-major rows).
// ---------------------------------------------------------------------------
__global__ void __launch_bounds__(256)
xw0_kernel(const float* __restrict__ x, const float* __restrict__ W0,
           float* __restrict__ t0) {
    __shared__ __align__(16) float xs[64 * FIN];   // 32 KB
    const int tid = threadIdx.x, lane = tid & 31, warp = tid >> 5;
    const size_t base = (size_t)blockIdx.x * 64;

    {
        const float4* s = reinterpret_cast<const float4*>(x + base * FIN);
        float4* d = reinterpret_cast<float4*>(xs);
#pragma unroll
        for (int i = tid; i < 64 * FIN / 4; i += 256) d[i] = s[i];
    }
    __syncthreads();

    ull acc[8] = {0, 0, 0, 0, 0, 0, 0, 0};   // (even-k sum, odd-k sum)
    const float* xr = xs + warp * 8 * FIN;
#pragma unroll 4
    for (int k = 0; k < FIN; k += 4) {
        float wa = __ldg(&W0[(k + 0) * HH + lane]);
        float wb = __ldg(&W0[(k + 1) * HH + lane]);
        float wc = __ldg(&W0[(k + 2) * HH + lane]);
        float wd = __ldg(&W0[(k + 3) * HH + lane]);
        ull wab = pack2(wa, wb), wcd = pack2(wc, wd);
#pragma unroll
        for (int j = 0; j < 8; j++) {
            double2 v = *reinterpret_cast<const double2*>(&xr[j * FIN + k]);
            fma2(acc[j], d2u(v.x), wab);
            fma2(acc[j], d2u(v.y), wcd);
        }
    }
    float* o = t0 + (base + (size_t)warp * 8) * HH + lane;
#pragma unroll
    for (int j = 0; j < 8; j++) o[j * HH] = hsum2(acc[j]);
}

// ---------------------------------------------------------------------------
// Kernel B: per-graph GCN agg1 + layers 2-4 + sort-pool + conv1/conv2
// (round-7 structure; matmul32 upgraded to f32x2)
// ---------------------------------------------------------------------------
struct Smem {
    alignas(16) float  h[MM * HH];     // 6400
    alignas(16) float  tmp[MM * HH];   // 6400
    float2 epack[EPG];                 // 3200
    float  lat[MM * DLAT];             // 19400 (stride 97: conflict-free col access)
    float  z1[16 * KK];                // 1920
    float  pooled[16 * 15];            // 960
    float  dinv[MM];
    float  h4v[MM];
    int    rp[MM + 1];
    int    cnt[MM];
    int    cnt2[MM];
    int    sel[KK];
    int    eraws[EPG];
    int    erawd[EPG];
};

// h[M,32](smem) @ W[32,32](global, L1-hot) -> tmp[M,32]. f32x2 k-pairs.
__device__ __forceinline__ void gcn_matmul32(const float* __restrict__ in,
                                             const float* __restrict__ Wg,
                                             float* __restrict__ tmp,
                                             int warp, int lane) {
    int nbase = warp * 7;
    if (nbase >= MM) return;
    int ncnt = MM - nbase; if (ncnt > 7) ncnt = 7;
    ull acc[7] = {0, 0, 0, 0, 0, 0, 0};
#pragma unroll
    for (int k = 0; k < HH; k += 4) {
        float wa = __ldg(&Wg[(k + 0) * HH + lane]);
        float wb = __ldg(&Wg[(k + 1) * HH + lane]);
        float wc = __ldg(&Wg[(k + 2) * HH + lane]);
        float wd = __ldg(&Wg[(k + 3) * HH + lane]);
        ull wab = pack2(wa, wb), wcd = pack2(wc, wd);
#pragma unroll
        for (int j = 0; j < 7; j++) {
            if (j < ncnt) {
                double2 v = *reinterpret_cast<const double2*>(&in[(nbase + j) * HH + k]);
                fma2(acc[j], d2u(v.x), wab);
                fma2(acc[j], d2u(v.y), wcd);
            }
        }
    }
    for (int j = 0; j < ncnt; j++) tmp[(nbase + j) * HH + lane] = hsum2(acc[j]);
}

// gather-aggregate (CSR by dst) + self loop + bias + tanh -> h and lat column block
__device__ __forceinline__ void gcn_agg(Smem& s, int coloff, float bias,
                                        int warp, int lane) {
    for (int n = warp; n < MM; n += 8) {
        float di = s.dinv[n];
        float a = s.tmp[n * HH + lane] * di * di;
        int e1 = s.rp[n + 1];
        for (int e = s.rp[n]; e < e1; e++) {
            float2 p = s.epack[e];
            a = fmaf(s.tmp[__float_as_int(p.x) * HH + lane], p.y, a);
        }
        float r = tanhf(a + bias);
        s.lat[n * DLAT + coloff + lane] = r;
        s.h[n * HH + lane] = r;
    }
}

__global__ void __launch_bounds__(256, 4)
graph_kernel(const float* __restrict__ t0, const int* __restrict__ ei,
             const float* __restrict__ b0,
             const float* __restrict__ W1, const float* __restrict__ b1,
             const float* __restrict__ W2, const float* __restrict__ b2,
             const float* __restrict__ W3, const float* __restrict__ b3,
             const float* __restrict__ C1w, const float* __restrict__ C1b,
             const float* __restrict__ C2w, const float* __restrict__ C2b,
             int E) {
    extern __shared__ __align__(16) char raw[];
    Smem& s = *reinterpret_cast<Smem*>(raw);
    const int tid = threadIdx.x, lane = tid & 31, warp = tid >> 5;
    const int g = blockIdx.x;

    // ---- stage t0 slice into tmp (coalesced), edges, counters ----
    {
        const float4* tsrc = reinterpret_cast<const float4*>(t0 + (size_t)g * MM * HH);
        float4* tdst = reinterpret_cast<float4*>(s.tmp);
        for (int i = tid; i < MM * HH / 4; i += 256) tdst[i] = tsrc[i];
    }
    if (tid < MM) { s.cnt[tid] = 1; s.cnt2[tid] = 0; }  // self loop in cnt
    const int ebase = g * EPG;
    for (int e = tid; e < EPG; e += 256) {
        s.eraws[e] = ei[ebase + e] - g * MM;
        s.erawd[e] = ei[E + ebase + e] - g * MM;
    }
    __syncthreads();

    // ---- degree count ----
    for (int e = tid; e < EPG; e += 256) atomicAdd(&s.cnt[s.erawd[e]], 1);
    __syncthreads();

    // ---- dinv + warp-parallel exclusive scan of (cnt-1) -> rp ----
    if (tid >= 64 && tid < 64 + MM) s.dinv[tid - 64] = rsqrtf((float)s.cnt[tid - 64]);
    if (warp == 0) {
        int a = (lane < MM) ? (s.cnt[lane] - 1) : 0;
        int b = (lane + 32 < MM) ? (s.cnt[lane + 32] - 1) : 0;
        int sa = a, sb = b;
#pragma unroll
        for (int o = 1; o < 32; o <<= 1) {
            int ta = __shfl_up_sync(0xffffffffu, sa, o);
            int tb = __shfl_up_sync(0xffffffffu, sb, o);
            if (lane >= o) { sa += ta; sb += tb; }
        }
        int tot_a = __shfl_sync(0xffffffffu, sa, 31);
        s.rp[lane] = sa - a;
        if (lane + 32 < MM) s.rp[lane + 32] = tot_a + sb - b;
        if (lane == 31) s.rp[MM] = tot_a + sb;
    }
    __syncthreads();

    // ---- build CSR grouped by dst ----
    for (int e = tid; e < EPG; e += 256) {
        int d = s.erawd[e], sl = s.eraws[e];
        int pos = s.rp[d] + atomicAdd(&s.cnt2[d], 1);
        s.epack[pos] = make_float2(__int_as_float(sl), s.dinv[sl] * s.dinv[d]);
    }
    __syncthreads();

    // ---- layer 1 aggregation (t0 already = x@W0) ----
    gcn_agg(s, 0, __ldg(&b0[lane]), warp, lane);
    __syncthreads();

    // ---- layers 2-3 ----
    gcn_matmul32(s.h, W1, s.tmp, warp, lane);
    __syncthreads();
    gcn_agg(s, 32, __ldg(&b1[lane]), warp, lane);
    __syncthreads();

    gcn_matmul32(s.h, W2, s.tmp, warp, lane);
    __syncthreads();
    gcn_agg(s, 64, __ldg(&b2[lane]), warp, lane);
    __syncthreads();

    // ---- layer 4: H=32 -> 1 ----
    {
        float w3 = __ldg(&W3[lane]);
        for (int n = warp; n < MM; n += 8) {
            float v = s.h[n * HH + lane] * w3;
#pragma unroll
            for (int o = 16; o; o >>= 1) v += __shfl_xor_sync(0xffffffffu, v, o);
            if (lane == 0) s.tmp[n] = v;
        }
    }
    __syncthreads();
    if (tid < MM) {
        int n = tid;
        float di = s.dinv[n];
        float a = s.tmp[n] * di * di;
        int e1 = s.rp[n + 1];
        for (int e = s.rp[n]; e < e1; e++) {
            float2 p = s.epack[e];
            a = fmaf(s.tmp[__float_as_int(p.x)], p.y, a);
        }
        float r = tanhf(a + __ldg(&b3[0]));
        s.lat[n * DLAT + 96] = r;
        s.h4v[n] = r;
    }
    __syncthreads();

    // ---- sort-pool: exact rank == stable argsort(-h4) ----
    if (tid < MM) {
        float vi = s.h4v[tid];
        int r = 0;
        for (int j = 0; j < MM; j++) {
            float vj = s.h4v[j];
            r += (vj > vi) || (vj == vi && j < tid);
        }
        if (r < KK) s.sel[r] = tid;
    }
    __syncthreads();

    // ---- conv1 (per-slot 97-dot) + relu ----
    for (int o = tid; o < 16 * KK; o += 256) {
        int t = o % KK, c = o / KK;
        const float* lr = &s.lat[s.sel[t] * DLAT];
        const float* cw = &C1w[c * DLAT];
        float a = __ldg(&C1b[c]);
#pragma unroll 4
        for (int d = 0; d < DLAT; d++) a = fmaf(lr[d], __ldg(&cw[d]), a);
        s.z1[c * KK + t] = fmaxf(a, 0.f);
    }
    __syncthreads();

    // ---- maxpool(2,2) ----
    if (tid < 16 * 15) {
        int u = tid % 15, c = tid / 15;
        s.pooled[c * 15 + u] = fmaxf(s.z1[c * KK + 2 * u], s.z1[c * KK + 2 * u + 1]);
    }
    __syncthreads();

    // ---- conv2 (16->32, k=5) + relu -> global scratch ----
    for (int o2 = tid; o2 < DDENSE; o2 += 256) {
        int o = o2 / 11, u = o2 % 11;
        float a = __ldg(&C2b[o]);
#pragma unroll
        for (int i = 0; i < 16; i++) {
            const float* pw = &C2w[(o * 16 + i) * 5];
            const float* pp = &s.pooled[i * 15 + u];
#pragma unroll
            for (int k2 = 0; k2 < 5; k2++) a = fmaf(pp[k2], __ldg(&pw[k2]), a);
        }
        g_z[(size_t)g * DDENSE + o2] = fmaxf(a, 0.f);
    }
}

// ---------------------------------------------------------------------------
// Kernel C: fused dense. 8 graphs / CTA, 128 threads (unchanged).
// ---------------------------------------------------------------------------
__global__ void __launch_bounds__(128)
dense_kernel(const float* __restrict__ L1w, const float* __restrict__ L1b,
             const float* __restrict__ L2w, const float* __restrict__ L2b,
             float* __restrict__ out) {
    __shared__ __align__(16) float zs[8][DDENSE];
    __shared__ float red[4][8];
    const int tid = threadIdx.x, lane = tid & 31, warp = tid >> 5;
    const int gbase = blockIdx.x * 8;

    {
        const float4* zsrc = reinterpret_cast<const float4*>(&g_z[(size_t)gbase * DDENSE]);
        float4* zdst = reinterpret_cast<float4*>(&zs[0][0]);
        for (int i = tid; i < 8 * DDENSE / 4; i += 128) zdst[i] = zsrc[i];
    }
    __syncthreads();

    const int ch = warp * 32 + lane;
    float acc[8];
    float l1b = __ldg(&L1b[ch]);
#pragma unroll
    for (int j = 0; j < 8; j++) acc[j] = l1b;

#pragma unroll 2
    for (int d = 0; d < DDENSE; d += 4) {
        float w0 = __ldg(&L1w[(d + 0) * 128 + ch]);
        float w1 = __ldg(&L1w[(d + 1) * 128 + ch]);
        float w2 = __ldg(&L1w[(d + 2) * 128 + ch]);
        float w3 = __ldg(&L1w[(d + 3) * 128 + ch]);
#pragma unroll
        for (int j = 0; j < 8; j++) {
            float4 zv = *reinterpret_cast<const float4*>(&zs[j][d]);
            acc[j] = fmaf(zv.x, w0, fmaf(zv.y, w1, fmaf(zv.z, w2, fmaf(zv.w, w3, acc[j]))));
        }
    }

    float w2v = __ldg(&L2w[ch]);
#pragma unroll
    for (int j = 0; j < 8; j++) {
        float p = fmaxf(acc[j], 0.f) * w2v;
#pragma unroll
        for (int o = 16; o; o >>= 1) p += __shfl_xor_sync(0xffffffffu, p, o);
        if (lane == 0) red[warp][j] = p;
    }
    __syncthreads();

    if (tid < 8) {
        out[gbase + tid] = red[0][tid] + red[1][tid] + red[2][tid] + red[3][tid]
                         + __ldg(&L2b[0]);
    }
}

extern "C" void kernel_launch(void* const* d_in, const int* in_sizes, int n_in,
                              void* d_out, int out_size) {
    const float* x   = (const float*)d_in[0];
    const int*   ei  = (const int*)d_in[1];
    // d_in[2] = batch (unused; graphs are contiguous equal-size blocks)
    const float* W0  = (const float*)d_in[3];
    const float* b0  = (const float*)d_in[4];
    const float* W1  = (const float*)d_in[5];
    const float* b1  = (const float*)d_in[6];
    const float* W2  = (const float*)d_in[7];
    const float* b2  = (const float*)d_in[8];
    const float* W3  = (const float*)d_in[9];
    const float* b3  = (const float*)d_in[10];
    const float* C1w = (const float*)d_in[11];
    const float* C1b = (const float*)d_in[12];
    const float* C2w = (const float*)d_in[13];
    const float* C2b = (const float*)d_in[14];
    const float* L1w = (const float*)d_in[15];
    const float* L1b = (const float*)d_in[16];
    const float* L2w = (const float*)d_in[17];
    const float* L2b = (const float*)d_in[18];

    const int E = in_sizes[1] / 2;

    float* t0;
    cudaGetSymbolAddress((void**)&t0, g_t0);

    const int smem = (int)sizeof(Smem);
    cudaFuncSetAttribute(graph_kernel, cudaFuncAttributeMaxDynamicSharedMemorySize, smem);

    xw0_kernel<<<NN / 64, 256>>>(x, W0, t0);
    graph_kernel<<<GG, 256, smem>>>(t0, ei, b0, W1, b1, W2, b2, W3, b3,
                                    C1w, C1b, C2w, C2b, E);
    dense_kernel<<<GG / 8, 128>>>(L1w, L1b, L2w, L2b, (float*)d_out);
}